// round 16
// baseline (speedup 1.0000x reference)
#include <cuda_runtime.h>
#include <cuda_bf16.h>

// Ball query: for each of NQ=32768 query points (p_grid), find first K=10
// points of x (NP=8192) with d2 <= RADIUS^2, ascending index order.
//
// Output (float32): [0..NQ*K) mapping (index as float), [NQ*K..NQ*K*4) coords.
//
// R16: cell lists (R15 build) + query binning + SMEM-staged scan.
//   kernel1 (1024 CTAs): [0,512) build point cell-lists (deterministic,
//     index-sorted); [512,1024) bin queries by cell into fixed-capacity bins.
//   bq (512 CTAs = cell x qseg): stage first 1536 list entries into SMEM,
//     8 warps process the bin's queries from SMEM (global fallback ~never).
// d2 expression and selection logic byte-identical to all passing rounds.

#define NP 8192
#define NQ 32768
#define KNN 10
#define R2C 0.0625f
#define MAP_ELEMS (NQ * KNN)
#define NCELLS 64
#define MAXN 4224
#define SLOPW 0.2501f
#define SEGS 8
#define SEGSZ (NP / SEGS)     // 1024
#define QSEGS 8
#define QSEGSZ (NQ / QSEGS)   // 4096
#define QCAP 128              // >= 64 avg + 8 sigma
#define SSTAGE 1536           // list entries staged in SMEM (24 KB)

__device__ float4 g_nbr[NCELLS][MAXN];
__device__ int    g_lidx[NCELLS][MAXN];
__device__ int    g_cnt[NCELLS];
__device__ int    g_qbin[NCELLS][QSEGS * QCAP];
__device__ int    g_qn[NCELLS][QSEGS];

// ---------------- kernel 1: point lists + query bins ----------------
__global__ void __launch_bounds__(128)
build_kernel(const float* __restrict__ x, const float* __restrict__ pg)
{
    if (blockIdx.x < NCELLS * SEGS) {
        // ---- point cell-list build (same as R15) ----
        __shared__ int s_red[4];
        __shared__ int s_wcnt[4];
        const int cell = blockIdx.x >> 3;
        const int seg  = blockIdx.x & 7;
        const int cz = cell & 3, cy = (cell >> 2) & 3, cx = (cell >> 4) & 3;
        const float lox = cx * 0.25f - SLOPW, hix = cx * 0.25f + 0.25f + SLOPW;
        const float loy = cy * 0.25f - SLOPW, hiy = cy * 0.25f + 0.25f + SLOPW;
        const float loz = cz * 0.25f - SLOPW, hiz = cz * 0.25f + 0.25f + SLOPW;

        const int lane = threadIdx.x & 31;
        const int warp = threadIdx.x >> 5;
        const unsigned lt = (1u << lane) - 1u;
        const int seg0 = seg * SEGSZ;

        int pre = 0;
        for (int base = 0; base < seg0; base += 128) {
            const int i = base + threadIdx.x;
            const float px = x[3 * i + 0];
            const float py = x[3 * i + 1];
            const float pz = x[3 * i + 2];
            pre += (px >= lox && px <= hix && py >= loy && py <= hiy &&
                    pz >= loz && pz <= hiz) ? 1 : 0;
        }
        for (int o = 16; o > 0; o >>= 1) pre += __shfl_down_sync(0xffffffffu, pre, o);
        if (lane == 0) s_red[warp] = pre;
        __syncthreads();
        const int block_off = s_red[0] + s_red[1] + s_red[2] + s_red[3];

        const int w0 = seg0 + warp * (SEGSZ / 4);
        const int w1 = w0 + (SEGSZ / 4);
        int c = 0;
        for (int base = w0; base < w1; base += 32) {
            const int i = base + lane;
            const float px = x[3 * i + 0];
            const float py = x[3 * i + 1];
            const float pz = x[3 * i + 2];
            const bool in = (px >= lox && px <= hix && py >= loy && py <= hiy &&
                             pz >= loz && pz <= hiz);
            c += __popc(__ballot_sync(0xffffffffu, in));
        }
        if (lane == 0) s_wcnt[warp] = c;
        __syncthreads();
        int off = block_off;
        for (int w = 0; w < warp; w++) off += s_wcnt[w];

        int cnt = 0;
        for (int base = w0; base < w1; base += 32) {
            const int i = base + lane;
            const float px = x[3 * i + 0];
            const float py = x[3 * i + 1];
            const float pz = x[3 * i + 2];
            const bool in = (px >= lox && px <= hix && py >= loy && py <= hiy &&
                             pz >= loz && pz <= hiz);
            const unsigned m = __ballot_sync(0xffffffffu, in);
            if (in) {
                const int pos = off + cnt + __popc(m & lt);
                if (pos < MAXN) {
                    const float ps = px * px + py * py + pz * pz;
                    g_nbr[cell][pos] = make_float4(px, py, pz, ps);
                    g_lidx[cell][pos] = i;
                }
            }
            cnt += __popc(m);
        }
        if (seg == SEGS - 1 && threadIdx.x == 0) {
            int tot = block_off + s_wcnt[0] + s_wcnt[1] + s_wcnt[2] + s_wcnt[3];
            g_cnt[cell] = tot < MAXN ? tot : MAXN;
        }
    } else {
        // ---- query binning: CTA = (cell, qseg) ----
        __shared__ int s_n;
        const int b = blockIdx.x - NCELLS * SEGS;
        const int cell = b >> 3;
        const int qseg = b & 7;
        if (threadIdx.x == 0) s_n = 0;
        __syncthreads();

        const int q0 = qseg * QSEGSZ;
        for (int base = q0; base < q0 + QSEGSZ; base += 128) {
            const int q = base + threadIdx.x;
            const float qx = pg[3 * q + 0];
            const float qy = pg[3 * q + 1];
            const float qz = pg[3 * q + 2];
            int cx = (int)(qx * 4.0f); cx = cx < 0 ? 0 : (cx > 3 ? 3 : cx);
            int cy = (int)(qy * 4.0f); cy = cy < 0 ? 0 : (cy > 3 ? 3 : cy);
            int cz = (int)(qz * 4.0f); cz = cz < 0 ? 0 : (cz > 3 ? 3 : cz);
            if ((cx * 4 + cy) * 4 + cz == cell) {
                const int slot = atomicAdd(&s_n, 1);
                if (slot < QCAP) g_qbin[cell][qseg * QCAP + slot] = q;
            }
        }
        __syncthreads();
        if (threadIdx.x == 0)
            g_qn[cell][qseg] = s_n < QCAP ? s_n : QCAP;
    }
}

// ---------------- kernel 2: ball query from SMEM-staged lists ----------------
__global__ void __launch_bounds__(256)
bq_kernel(const float* __restrict__ pg, float* __restrict__ out)
{
    __shared__ float4 s_lst[SSTAGE];          // 24 KB
    __shared__ int scratch[8][16];

    const int cell = blockIdx.x >> 3;
    const int qseg = blockIdx.x & 7;
    const int n      = g_cnt[cell];
    const int nstage = n < SSTAGE ? n : SSTAGE;
    const float4* __restrict__ lst  = g_nbr[cell];
    const int*    __restrict__ lidx = g_lidx[cell];

    for (int i = threadIdx.x; i < nstage; i += blockDim.x)
        s_lst[i] = lst[i];
    __syncthreads();

    const int m = g_qn[cell][qseg];
    const int* __restrict__ qb = &g_qbin[cell][qseg * QCAP];

    const int lane = threadIdx.x & 31;
    const int warp = threadIdx.x >> 5;
    const unsigned lt_mask = (1u << lane) - 1u;

    for (int j = warp; j < m; j += 8) {
        const int q = qb[j];
        const float qx = pg[3 * q + 0];
        const float qy = pg[3 * q + 1];
        const float qz = pg[3 * q + 2];
        const float q2 = qx * qx + qy * qy + qz * qz;

        int cnt = 0;

        // ---- phase 1: staged SMEM scan, 64 entries / iter, 2 streams ----
        for (int base = 0; base < nstage; base += 64) {
            const int eA = base + lane;
            const int eB = base + 32 + lane;
            const float4 A = (eA < nstage) ? s_lst[eA] : make_float4(0.f, 0.f, 0.f, 1e30f);
            const float4 B = (eB < nstage) ? s_lst[eB] : make_float4(0.f, 0.f, 0.f, 1e30f);

            const float dotA = qx * A.x + qy * A.y + qz * A.z;
            const float d2A  = q2 + A.w - 2.0f * dotA;
            const float dotB = qx * B.x + qy * B.y + qz * B.z;
            const float d2B  = q2 + B.w - 2.0f * dotB;

            const bool vA = (d2A <= R2C);
            const bool vB = (d2B <= R2C);
            const unsigned mA = __ballot_sync(0xffffffffu, vA);
            const unsigned mB = __ballot_sync(0xffffffffu, vB);

            if (mA | mB) {
                if (vA) {
                    const int slot = cnt + __popc(mA & lt_mask);
                    if (slot < KNN) scratch[warp][slot] = eA;
                }
                const int cA = cnt + __popc(mA);
                if (vB) {
                    const int slot = cA + __popc(mB & lt_mask);
                    if (slot < KNN) scratch[warp][slot] = eB;
                }
                cnt = cA + __popc(mB);
                if (cnt >= KNN) break;   // warp-uniform
            }
        }

        // ---- phase 2 (rare): rest of list from global ----
        if (cnt < KNN && n > nstage) {
            for (int base = nstage; base < n; base += 32) {
                const int e = base + lane;
                const float4 P = (e < n) ? lst[e] : make_float4(0.f, 0.f, 0.f, 1e30f);
                const float dot = qx * P.x + qy * P.y + qz * P.z;
                const float d2  = q2 + P.w - 2.0f * dot;
                const bool v = (d2 <= R2C);
                const unsigned mk = __ballot_sync(0xffffffffu, v);
                if (v) {
                    const int slot = cnt + __popc(mk & lt_mask);
                    if (slot < KNN) scratch[warp][slot] = e;
                }
                cnt += __popc(mk);
                if (cnt >= KNN) break;
            }
        }

        __syncwarp();

        // ---- epilogue: lanes 0..9 emit mapping + coords ----
        const int c = cnt < KNN ? cnt : KNN;
        if (lane < KNN) {
            const bool found = (lane < c);
            int idx = 0;
            float px = 0.0f, py = 0.0f, pz = 0.0f;
            if (found) {
                const int e = scratch[warp][lane];
                const float4 P = (e < nstage) ? s_lst[e] : lst[e];
                px = P.x; py = P.y; pz = P.z;
                idx = lidx[e];
            }
            out[(size_t)q * KNN + lane] = found ? (float)idx : 0.0f;
            float* oc = out + MAP_ELEMS + ((size_t)q * KNN + lane) * 3;
            oc[0] = px; oc[1] = py; oc[2] = pz;
        }
        __syncwarp();   // scratch reuse safety
    }
}

extern "C" void kernel_launch(void* const* d_in, const int* in_sizes, int n_in,
                              void* d_out, int out_size)
{
    const float* x  = (const float*)d_in[0];   // (1, 8192, 3)
    const float* pg = (const float*)d_in[1];   // (1, 64, 32, 16, 3)
    if (n_in >= 2 && in_sizes[0] == NQ * 3 && in_sizes[1] == NP * 3) {
        const float* t = x; x = pg; pg = t;
    }
    float* out = (float*)d_out;

    build_kernel<<<NCELLS * SEGS + NCELLS * QSEGS, 128>>>(x, pg);
    bq_kernel<<<NCELLS * QSEGS, 256>>>(pg, out);
}

// round 17
// speedup vs baseline: 1.2000x; 1.2000x over previous
#include <cuda_runtime.h>
#include <cuda_bf16.h>

// Ball query: for each of NQ=32768 query points (p_grid), find first K=10
// points of x (NP=8192) with d2 <= RADIUS^2, ascending index order.
//
// Output (float32): [0..NQ*K) mapping (index as float), [NQ*K..NQ*K*4) coords.
//
// R17 = R15 structure (cell lists + warp-per-query scan; best bq) with:
//   1. build split into count + compact kernels (no phase-0 prefix rescan)
//   2. bq software-pipelined ACROSS queries: next query's pg load, cell
//      lookup and chunk-0 list loads issue before current query's compute,
//      hiding the L2 round-trip that dominated R15's bq.
// d2 expression and selection logic byte-identical to all passing rounds.

#define NP 8192
#define NQ 32768
#define KNN 10
#define R2C 0.0625f
#define MAP_ELEMS (NQ * KNN)
#define NCELLS 64
#define MAXN 4224
#define SLOPW 0.2501f
#define SEGS 8
#define SEGSZ (NP / SEGS)     // 1024

__device__ float4 g_nbr[NCELLS][MAXN];
__device__ int    g_lidx[NCELLS][MAXN];
__device__ int    g_cnt[NCELLS];
__device__ int    g_scnt[NCELLS][SEGS];

// ---------------- kernel 1: per-(cell,seg) counts ----------------
__global__ void __launch_bounds__(128)
count_kernel(const float* __restrict__ x)
{
    __shared__ int s_red[4];
    const int cell = blockIdx.x >> 3;
    const int seg  = blockIdx.x & 7;
    const int cz = cell & 3, cy = (cell >> 2) & 3, cx = (cell >> 4) & 3;
    const float lox = cx * 0.25f - SLOPW, hix = cx * 0.25f + 0.25f + SLOPW;
    const float loy = cy * 0.25f - SLOPW, hiy = cy * 0.25f + 0.25f + SLOPW;
    const float loz = cz * 0.25f - SLOPW, hiz = cz * 0.25f + 0.25f + SLOPW;

    const int lane = threadIdx.x & 31;
    const int warp = threadIdx.x >> 5;
    const int seg0 = seg * SEGSZ;

    int c = 0;
    for (int base = seg0; base < seg0 + SEGSZ; base += 128) {
        const int i = base + threadIdx.x;
        const float px = x[3 * i + 0];
        const float py = x[3 * i + 1];
        const float pz = x[3 * i + 2];
        c += (px >= lox && px <= hix && py >= loy && py <= hiy &&
              pz >= loz && pz <= hiz) ? 1 : 0;
    }
    for (int o = 16; o > 0; o >>= 1) c += __shfl_down_sync(0xffffffffu, c, o);
    if (lane == 0) s_red[warp] = c;
    __syncthreads();
    if (threadIdx.x == 0)
        g_scnt[cell][seg] = s_red[0] + s_red[1] + s_red[2] + s_red[3];
}

// ---------------- kernel 2: ordered compact ----------------
__global__ void __launch_bounds__(128)
compact_kernel(const float* __restrict__ x)
{
    __shared__ int s_wcnt[4];
    const int cell = blockIdx.x >> 3;
    const int seg  = blockIdx.x & 7;
    const int cz = cell & 3, cy = (cell >> 2) & 3, cx = (cell >> 4) & 3;
    const float lox = cx * 0.25f - SLOPW, hix = cx * 0.25f + 0.25f + SLOPW;
    const float loy = cy * 0.25f - SLOPW, hiy = cy * 0.25f + 0.25f + SLOPW;
    const float loz = cz * 0.25f - SLOPW, hiz = cz * 0.25f + 0.25f + SLOPW;

    const int lane = threadIdx.x & 31;
    const int warp = threadIdx.x >> 5;
    const unsigned lt = (1u << lane) - 1u;
    const int seg0 = seg * SEGSZ;

    // prefix over earlier segments of this cell (8 small loads)
    int block_off = 0;
    for (int s = 0; s < seg; s++) block_off += g_scnt[cell][s];

    // per-warp counts within this segment
    const int w0 = seg0 + warp * (SEGSZ / 4);
    const int w1 = w0 + (SEGSZ / 4);
    int c = 0;
    for (int base = w0; base < w1; base += 32) {
        const int i = base + lane;
        const float px = x[3 * i + 0];
        const float py = x[3 * i + 1];
        const float pz = x[3 * i + 2];
        const bool in = (px >= lox && px <= hix && py >= loy && py <= hiy &&
                         pz >= loz && pz <= hiz);
        c += __popc(__ballot_sync(0xffffffffu, in));
    }
    if (lane == 0) s_wcnt[warp] = c;
    __syncthreads();
    int off = block_off;
    for (int w = 0; w < warp; w++) off += s_wcnt[w];

    // ordered compact
    int cnt = 0;
    for (int base = w0; base < w1; base += 32) {
        const int i = base + lane;
        const float px = x[3 * i + 0];
        const float py = x[3 * i + 1];
        const float pz = x[3 * i + 2];
        const bool in = (px >= lox && px <= hix && py >= loy && py <= hiy &&
                         pz >= loz && pz <= hiz);
        const unsigned m = __ballot_sync(0xffffffffu, in);
        if (in) {
            const int pos = off + cnt + __popc(m & lt);
            if (pos < MAXN) {
                const float ps = px * px + py * py + pz * pz;
                g_nbr[cell][pos] = make_float4(px, py, pz, ps);
                g_lidx[cell][pos] = i;
            }
        }
        cnt += __popc(m);
    }

    if (seg == SEGS - 1 && threadIdx.x == 0) {
        int tot = block_off + s_wcnt[0] + s_wcnt[1] + s_wcnt[2] + s_wcnt[3];
        g_cnt[cell] = tot < MAXN ? tot : MAXN;
    }
}

// ---------------- kernel 3: ball query, pipelined across queries ----------------
__global__ void __launch_bounds__(256)
bq_kernel(const float* __restrict__ pg, float* __restrict__ out)
{
    __shared__ int scratch[8][16];
    __shared__ int s_ccnt[NCELLS];

    if (threadIdx.x < NCELLS) s_ccnt[threadIdx.x] = g_cnt[threadIdx.x];
    __syncthreads();

    const int lane   = threadIdx.x & 31;
    const int warp   = threadIdx.x >> 5;
    const int gwarp  = (blockIdx.x * blockDim.x + threadIdx.x) >> 5;
    const int nwarps = (gridDim.x * blockDim.x) >> 5;
    const unsigned lt_mask = (1u << lane) - 1u;

    const float4 SENT = make_float4(0.f, 0.f, 0.f, 1e30f);

    // ---- prefetch state for the first query ----
    int q = gwarp;
    float qx = 0.f, qy = 0.f, qz = 0.f;
    int cell = 0, n = 0;
    float4 A0 = SENT, B0 = SENT;
    if (q < NQ) {
        qx = pg[3 * q + 0];
        qy = pg[3 * q + 1];
        qz = pg[3 * q + 2];
        int cx = (int)(qx * 4.0f); cx = cx < 0 ? 0 : (cx > 3 ? 3 : cx);
        int cy = (int)(qy * 4.0f); cy = cy < 0 ? 0 : (cy > 3 ? 3 : cy);
        int cz = (int)(qz * 4.0f); cz = cz < 0 ? 0 : (cz > 3 ? 3 : cz);
        cell = (cx * 4 + cy) * 4 + cz;
        n = s_ccnt[cell];
        A0 = (lane      < n) ? g_nbr[cell][lane]      : SENT;
        B0 = (lane + 32 < n) ? g_nbr[cell][lane + 32] : SENT;
    }

    while (q < NQ) {
        // current query state
        const float cqx = qx, cqy = qy, cqz = qz;
        const float q2 = cqx * cqx + cqy * cqy + cqz * cqz;
        const int ccell = cell, cn = n;
        const float4 cA0 = A0, cB0 = B0;
        const float4* __restrict__ lst  = g_nbr[ccell];
        const int*    __restrict__ lidx = g_lidx[ccell];
        const int cq = q;

        // ---- issue next query's prefetch NOW (independent loads) ----
        const int qn = q + nwarps;
        if (qn < NQ) {
            qx = pg[3 * qn + 0];
            qy = pg[3 * qn + 1];
            qz = pg[3 * qn + 2];
            int cx = (int)(qx * 4.0f); cx = cx < 0 ? 0 : (cx > 3 ? 3 : cx);
            int cy = (int)(qy * 4.0f); cy = cy < 0 ? 0 : (cy > 3 ? 3 : cy);
            int cz = (int)(qz * 4.0f); cz = cz < 0 ? 0 : (cz > 3 ? 3 : cz);
            cell = (cx * 4 + cy) * 4 + cz;
            n = s_ccnt[cell];
            A0 = (lane      < n) ? g_nbr[cell][lane]      : SENT;
            B0 = (lane + 32 < n) ? g_nbr[cell][lane + 32] : SENT;
        }
        q = qn;

        // ---- scan current query's cell list ----
        int cnt = 0;
        {
            // chunk 0 from prefetched registers
            const float dotA = cqx * cA0.x + cqy * cA0.y + cqz * cA0.z;
            const float d2A  = q2 + cA0.w - 2.0f * dotA;
            const float dotB = cqx * cB0.x + cqy * cB0.y + cqz * cB0.z;
            const float d2B  = q2 + cB0.w - 2.0f * dotB;
            const bool vA = (d2A <= R2C);
            const bool vB = (d2B <= R2C);
            const unsigned mA = __ballot_sync(0xffffffffu, vA);
            const unsigned mB = __ballot_sync(0xffffffffu, vB);
            if (mA | mB) {
                if (vA) {
                    const int slot = cnt + __popc(mA & lt_mask);
                    if (slot < KNN) scratch[warp][slot] = lane;
                }
                const int cA = cnt + __popc(mA);
                if (vB) {
                    const int slot = cA + __popc(mB & lt_mask);
                    if (slot < KNN) scratch[warp][slot] = 32 + lane;
                }
                cnt = cA + __popc(mB);
            }
        }

        // remaining chunks (only if needed)
        if (cnt < KNN) {
            for (int base = 64; base < cn; base += 64) {
                const int eA = base + lane;
                const int eB = base + 32 + lane;
                const float4 A = (eA < cn) ? lst[eA] : SENT;
                const float4 B = (eB < cn) ? lst[eB] : SENT;

                const float dotA = cqx * A.x + cqy * A.y + cqz * A.z;
                const float d2A  = q2 + A.w - 2.0f * dotA;
                const float dotB = cqx * B.x + cqy * B.y + cqz * B.z;
                const float d2B  = q2 + B.w - 2.0f * dotB;

                const bool vA = (d2A <= R2C);
                const bool vB = (d2B <= R2C);
                const unsigned mA = __ballot_sync(0xffffffffu, vA);
                const unsigned mB = __ballot_sync(0xffffffffu, vB);

                if (mA | mB) {
                    if (vA) {
                        const int slot = cnt + __popc(mA & lt_mask);
                        if (slot < KNN) scratch[warp][slot] = eA;
                    }
                    const int cA = cnt + __popc(mA);
                    if (vB) {
                        const int slot = cA + __popc(mB & lt_mask);
                        if (slot < KNN) scratch[warp][slot] = eB;
                    }
                    cnt = cA + __popc(mB);
                    if (cnt >= KNN) break;   // warp-uniform
                }
            }
        }

        __syncwarp();

        // ---- epilogue: lanes 0..9 emit mapping + coords ----
        const int c = cnt < KNN ? cnt : KNN;
        if (lane < KNN) {
            const bool found = (lane < c);
            int idx = 0;
            float px = 0.0f, py = 0.0f, pz = 0.0f;
            if (found) {
                const int e = scratch[warp][lane];
                const float4 P = lst[e];
                px = P.x; py = P.y; pz = P.z;
                idx = lidx[e];
            }
            out[(size_t)cq * KNN + lane] = found ? (float)idx : 0.0f;
            float* oc = out + MAP_ELEMS + ((size_t)cq * KNN + lane) * 3;
            oc[0] = px; oc[1] = py; oc[2] = pz;
        }
        __syncwarp();   // scratch reuse safety
    }
}

extern "C" void kernel_launch(void* const* d_in, const int* in_sizes, int n_in,
                              void* d_out, int out_size)
{
    const float* x  = (const float*)d_in[0];   // (1, 8192, 3)
    const float* pg = (const float*)d_in[1];   // (1, 64, 32, 16, 3)
    if (n_in >= 2 && in_sizes[0] == NQ * 3 && in_sizes[1] == NP * 3) {
        const float* t = x; x = pg; pg = t;
    }
    float* out = (float*)d_out;

    count_kernel<<<NCELLS * SEGS, 128>>>(x);
    compact_kernel<<<NCELLS * SEGS, 128>>>(x);
    bq_kernel<<<888, 256>>>(pg, out);
}